// round 1
// baseline (speedup 1.0000x reference)
#include <cuda_runtime.h>

#define NUM_CLASSES 32
#define MAX_DET     100
#define CONF        0.25f
#define IOU_THR     0.45f
#define BATCH       64
#define ANCHORS     8400
#define NT          512
#define NWARPS      (NT / 32)

// dynamic smem layout: float4 boxes[8400] | float sc[8400] | u8 cls[8400]
#define SMEM_BYTES (ANCHORS * 16 + ANCHORS * 4 + ANCHORS)

__global__ __launch_bounds__(NT, 1)
void yolo_nms_kernel(const float* __restrict__ in, float* __restrict__ out)
{
    extern __shared__ char smem[];
    float4* sbox = reinterpret_cast<float4*>(smem);
    float*  ssc  = reinterpret_cast<float*>(smem + ANCHORS * 16);
    unsigned char* scls = reinterpret_cast<unsigned char*>(smem + ANCHORS * 16 + ANCHORS * 4);

    __shared__ float red_v[NWARPS];
    __shared__ int   red_i[NWARPS];
    __shared__ float s_best_v;
    __shared__ int   s_best_i;

    const int b   = blockIdx.x;
    const int tid = threadIdx.x;
    const float* base = in + (size_t)b * (4 + NUM_CLASSES) * ANCHORS;

    // ---- Phase 1: decode boxes, class max/argmax, conf mask -> smem ----
    for (int a = tid; a < ANCHORS; a += NT) {
        float xc = base[0 * ANCHORS + a];
        float yc = base[1 * ANCHORS + a];
        float w  = base[2 * ANCHORS + a];
        float h  = base[3 * ANCHORS + a];

        float bs = base[4 * ANCHORS + a];
        int   bc = 0;
        #pragma unroll
        for (int c = 1; c < NUM_CLASSES; c++) {
            float v = base[(4 + c) * ANCHORS + a];
            if (v > bs) { bs = v; bc = c; }   // strict > keeps first max (jnp.argmax)
        }

        float hw = w * 0.5f;
        float hh = h * 0.5f;
        float y1 = fminf(fmaxf(yc - hh, 0.0f), 1.0f);
        float x1 = fminf(fmaxf(xc - hw, 0.0f), 1.0f);
        float y2 = fminf(fmaxf(yc + hh, 0.0f), 1.0f);
        float x2 = fminf(fmaxf(xc + hw, 0.0f), 1.0f);

        sbox[a] = make_float4(y1, x1, y2, x2);
        ssc[a]  = (bs >= CONF) ? bs : -1.0f;
        scls[a] = (unsigned char)bc;
    }
    __syncthreads();

    float* out_boxes = out + (size_t)b * MAX_DET * 4;
    float* out_cls   = out + (size_t)BATCH * MAX_DET * 4 + (size_t)b * MAX_DET;
    float* out_sc    = out + (size_t)BATCH * MAX_DET * 5 + (size_t)b * MAX_DET;
    float* out_nd    = out + (size_t)BATCH * MAX_DET * 6 + b;

    // ---- Phase 2: greedy NMS (ok is monotone -> break + tail zero-fill) ----
    int ndet = 0;
    for (int it = 0; it < MAX_DET; it++) {
        // block argmax with first-max-index tie break
        float bv = -2.0f;
        int   bi = ANCHORS;
        for (int a = tid; a < ANCHORS; a += NT) {
            float v = ssc[a];
            if (v > bv) { bv = v; bi = a; }   // ascending a, strict > keeps smallest idx
        }
        #pragma unroll
        for (int off = 16; off > 0; off >>= 1) {
            float ov = __shfl_down_sync(0xffffffffu, bv, off);
            int   oi = __shfl_down_sync(0xffffffffu, bi, off);
            if (ov > bv || (ov == bv && oi < bi)) { bv = ov; bi = oi; }
        }
        if ((tid & 31) == 0) { red_v[tid >> 5] = bv; red_i[tid >> 5] = bi; }
        __syncthreads();
        if (tid < 32) {
            bv = (tid < NWARPS) ? red_v[tid] : -2.0f;
            bi = (tid < NWARPS) ? red_i[tid] : ANCHORS;
            #pragma unroll
            for (int off = 16; off > 0; off >>= 1) {
                float ov = __shfl_down_sync(0xffffffffu, bv, off);
                int   oi = __shfl_down_sync(0xffffffffu, bi, off);
                if (ov > bv || (ov == bv && oi < bi)) { bv = ov; bi = oi; }
            }
            if (tid == 0) { s_best_v = bv; s_best_i = bi; }
        }
        __syncthreads();

        float s = s_best_v;
        if (s <= 0.0f) break;               // all threads agree -> uniform break
        int idx = s_best_i;
        float4 bb = sbox[idx];

        if (tid == 0) {
            out_boxes[it * 4 + 0] = bb.x;
            out_boxes[it * 4 + 1] = bb.y;
            out_boxes[it * 4 + 2] = bb.z;
            out_boxes[it * 4 + 3] = bb.w;
            out_cls[it] = (float)scls[idx];
            out_sc[it]  = s;
        }

        float area_a = (bb.z - bb.x) * (bb.w - bb.y);
        for (int a = tid; a < ANCHORS; a += NT) {
            float4 ob = sbox[a];
            float yy1 = fmaxf(bb.x, ob.x);
            float xx1 = fmaxf(bb.y, ob.y);
            float yy2 = fminf(bb.z, ob.z);
            float xx2 = fminf(bb.w, ob.w);
            float inter  = fmaxf(yy2 - yy1, 0.0f) * fmaxf(xx2 - xx1, 0.0f);
            float area_b = (ob.z - ob.x) * (ob.w - ob.y);
            float uni    = area_a + area_b - inter;
            float iou    = (uni > 0.0f) ? (inter / uni) : 0.0f;
            if (iou > IOU_THR || a == idx) ssc[a] = -1.0f;
        }
        ndet++;
        __syncthreads();
    }

    // tail zero-fill (out buffer is poisoned, reference emits zeros when !ok)
    for (int i = ndet + tid; i < MAX_DET; i += NT) {
        out_boxes[i * 4 + 0] = 0.0f;
        out_boxes[i * 4 + 1] = 0.0f;
        out_boxes[i * 4 + 2] = 0.0f;
        out_boxes[i * 4 + 3] = 0.0f;
        out_cls[i] = 0.0f;
        out_sc[i]  = 0.0f;
    }
    if (tid == 0) *out_nd = (float)ndet;
}

extern "C" void kernel_launch(void* const* d_in, const int* in_sizes, int n_in,
                              void* d_out, int out_size)
{
    (void)in_sizes; (void)n_in; (void)out_size;
    const float* in = (const float*)d_in[0];
    float* out = (float*)d_out;

    cudaFuncSetAttribute(yolo_nms_kernel,
                         cudaFuncAttributeMaxDynamicSharedMemorySize, SMEM_BYTES);
    yolo_nms_kernel<<<BATCH, NT, SMEM_BYTES>>>(in, out);
}

// round 2
// speedup vs baseline: 2.5443x; 2.5443x over previous
#include <cuda_runtime.h>

#define NUM_CLASSES 32
#define MAX_DET     100
#define CONF        0.25f
#define IOU_C       0.45f
#define HC          1.4901161193847656e-8f   // 2^-26 = half-ulp(0.45f)
#define BATCH       64
#define ANCHORS     8400
#define NT          512
#define KPT         17
#define PADDED      (NT * KPT)               // 8704
#define NWARPS      (NT / 32)

// dynamic smem: float4 boxes[8704] | float sc[8704] | u8 cls[8704]
#define SMEM_BYTES (PADDED * 16 + PADDED * 4 + PADDED)

__global__ __launch_bounds__(NT, 1)
void yolo_nms_kernel(const float* __restrict__ in, float* __restrict__ out)
{
    extern __shared__ char smem[];
    float4* sbox = reinterpret_cast<float4*>(smem);
    float*  ssc  = reinterpret_cast<float*>(smem + PADDED * 16);
    unsigned char* scls = reinterpret_cast<unsigned char*>(smem + PADDED * 20);

    __shared__ float red_v[NWARPS];
    __shared__ int   red_i[NWARPS];
    __shared__ float s_best_v;
    __shared__ int   s_best_i;

    const int b   = blockIdx.x;
    const int tid = threadIdx.x;
    const float* base = in + (size_t)b * (4 + NUM_CLASSES) * ANCHORS;

    // ---- Phase 1: decode + class argmax + conf mask -> smem (coalesced) ----
    for (int a = tid; a < PADDED; a += NT) {
        if (a < ANCHORS) {
            float xc = base[0 * ANCHORS + a];
            float yc = base[1 * ANCHORS + a];
            float w  = base[2 * ANCHORS + a];
            float h  = base[3 * ANCHORS + a];

            float bs = base[4 * ANCHORS + a];
            int   bc = 0;
            #pragma unroll
            for (int c = 1; c < NUM_CLASSES; c++) {
                float v = base[(4 + c) * ANCHORS + a];
                if (v > bs) { bs = v; bc = c; }   // strict > = first max (jnp.argmax)
            }

            float hw = w * 0.5f;
            float hh = h * 0.5f;
            float y1 = fminf(fmaxf(yc - hh, 0.0f), 1.0f);
            float x1 = fminf(fmaxf(xc - hw, 0.0f), 1.0f);
            float y2 = fminf(fmaxf(yc + hh, 0.0f), 1.0f);
            float x2 = fminf(fmaxf(xc + hw, 0.0f), 1.0f);

            sbox[a] = make_float4(y1, x1, y2, x2);
            ssc[a]  = (bs >= CONF) ? bs : -1.0f;
            scls[a] = (unsigned char)bc;
        } else {
            sbox[a] = make_float4(0.0f, 0.0f, 0.0f, 0.0f);
            ssc[a]  = -1.0f;
            scls[a] = 0;
        }
    }
    __syncthreads();

    // ---- Load blocked slice into registers: thread t owns anchors [t*17, t*17+17) ----
    float ry1[KPT], rx1[KPT], ry2[KPT], rx2[KPT], rsc[KPT];
    #pragma unroll
    for (int k = 0; k < KPT; k++) {
        float4 v = sbox[tid * KPT + k];
        ry1[k] = v.x; rx1[k] = v.y; ry2[k] = v.z; rx2[k] = v.w;
        rsc[k] = ssc[tid * KPT + k];
    }

    // initial per-thread argmax (ascending k, strict > = smallest index on tie)
    float tmax = -2.0f; int tbi = PADDED;
    #pragma unroll
    for (int k = 0; k < KPT; k++)
        if (rsc[k] > tmax) { tmax = rsc[k]; tbi = tid * KPT + k; }

    float* out_boxes = out + (size_t)b * MAX_DET * 4;
    float* out_cls   = out + (size_t)BATCH * MAX_DET * 4 + (size_t)b * MAX_DET;
    float* out_sc    = out + (size_t)BATCH * MAX_DET * 5 + (size_t)b * MAX_DET;
    float* out_nd    = out + (size_t)BATCH * MAX_DET * 6 + b;

    // ---- Phase 2: greedy NMS, suppress fused with next argmax ----
    int ndet = 0;
    for (int it = 0; it < MAX_DET; it++) {
        // block-wide argmax reduce of (tmax, tbi), tie -> smaller index
        float bv = tmax; int bi = tbi;
        #pragma unroll
        for (int off = 16; off > 0; off >>= 1) {
            float ov = __shfl_down_sync(0xffffffffu, bv, off);
            int   oi = __shfl_down_sync(0xffffffffu, bi, off);
            if (ov > bv || (ov == bv && oi < bi)) { bv = ov; bi = oi; }
        }
        if ((tid & 31) == 0) { red_v[tid >> 5] = bv; red_i[tid >> 5] = bi; }
        __syncthreads();
        if (tid < 32) {
            bv = (tid < NWARPS) ? red_v[tid] : -2.0f;
            bi = (tid < NWARPS) ? red_i[tid] : PADDED;
            #pragma unroll
            for (int off = 8; off > 0; off >>= 1) {
                float ov = __shfl_down_sync(0xffffffffu, bv, off);
                int   oi = __shfl_down_sync(0xffffffffu, bi, off);
                if (ov > bv || (ov == bv && oi < bi)) { bv = ov; bi = oi; }
            }
            if (tid == 0) { s_best_v = bv; s_best_i = bi; }
        }
        __syncthreads();

        float s = s_best_v;
        if (s <= 0.0f) break;               // uniform break
        int idx = s_best_i;
        float4 bb = sbox[idx];              // broadcast LDS, conflict-free

        if (tid == 0) {
            out_boxes[it * 4 + 0] = bb.x;
            out_boxes[it * 4 + 1] = bb.y;
            out_boxes[it * 4 + 2] = bb.z;
            out_boxes[it * 4 + 3] = bb.w;
            out_cls[it] = (float)scls[idx];
            out_sc[it]  = s;
        }

        // fused suppression + next-winner argmax (pure register math)
        if (tmax > 0.0f) {                   // all my anchors dead -> stale (tmax,tbi) still exact
            float aa = (bb.z - bb.x) * (bb.w - bb.y);
            float nmax = -2.0f; int nbi = PADDED;
            #pragma unroll
            for (int k = 0; k < KPT; k++) {
                int g = tid * KPT + k;
                float v = rsc[k];
                float iy1 = fmaxf(bb.x, ry1[k]);
                float ix1 = fmaxf(bb.y, rx1[k]);
                float iy2 = fminf(bb.z, ry2[k]);
                float ix2 = fminf(bb.w, rx2[k]);
                float dh  = fmaxf(iy2 - iy1, 0.0f);
                float dw  = fmaxf(ix2 - ix1, 0.0f);
                float inter = dh * dw;
                float ab  = (ry2[k] - ry1[k]) * (rx2[k] - rx1[k]);
                float uni = aa + ab - inter;
                // exact fl(inter/uni) > 0.45f without the division:
                //   fl(q) > c  <=>  q > c + 2^-26  <=>  inter - c*uni > uni*2^-26
                float d = fmaf(-IOU_C, uni, inter);
                bool sup = (g == idx) || ((uni > 0.0f) && (d > uni * HC));
                v = sup ? -1.0f : v;
                rsc[k] = v;
                if (v > nmax) { nmax = v; nbi = g; }
            }
            tmax = nmax; tbi = nbi;
        }
        ndet++;
    }

    // tail zero-fill (reference emits zeros for !ok slots)
    for (int i = ndet + tid; i < MAX_DET; i += NT) {
        out_boxes[i * 4 + 0] = 0.0f;
        out_boxes[i * 4 + 1] = 0.0f;
        out_boxes[i * 4 + 2] = 0.0f;
        out_boxes[i * 4 + 3] = 0.0f;
        out_cls[i] = 0.0f;
        out_sc[i]  = 0.0f;
    }
    if (tid == 0) *out_nd = (float)ndet;
}

extern "C" void kernel_launch(void* const* d_in, const int* in_sizes, int n_in,
                              void* d_out, int out_size)
{
    (void)in_sizes; (void)n_in; (void)out_size;
    const float* in = (const float*)d_in[0];
    float* out = (float*)d_out;

    cudaFuncSetAttribute(yolo_nms_kernel,
                         cudaFuncAttributeMaxDynamicSharedMemorySize, SMEM_BYTES);
    yolo_nms_kernel<<<BATCH, NT, SMEM_BYTES>>>(in, out);
}

// round 3
// speedup vs baseline: 3.1121x; 1.2232x over previous
#include <cuda_runtime.h>

#define NUM_CLASSES 32
#define MAX_DET     100
#define CONF        0.25f
#define IOU_C       0.45f
#define HC          1.4901161193847656e-8f   // 2^-26 = half-ulp(0.45f)
#define BATCH       64
#define ANCHORS     8400
#define NT          512
#define KPT         17
#define PADDED      (NT * KPT)               // 8704
#define NWARPS      (NT / 32)
#define NEG_INF_I   ((int)0x80000000)

// dynamic smem: float4 boxes[8704] | float sc[8704] | u8 cls[8704]
#define SMEM_BYTES (PADDED * 16 + PADDED * 4 + PADDED)

__global__ __launch_bounds__(NT, 1)
void yolo_nms_kernel(const float* __restrict__ in, float* __restrict__ out)
{
    extern __shared__ char smem[];
    float4* sbox = reinterpret_cast<float4*>(smem);
    float*  ssc  = reinterpret_cast<float*>(smem + PADDED * 16);
    unsigned char* scls = reinterpret_cast<unsigned char*>(smem + PADDED * 20);

    __shared__ int red_k[2][NWARPS];   // double-buffered warp winners
    __shared__ int red_i[2][NWARPS];

    const int b   = blockIdx.x;
    const int tid = threadIdx.x;
    const unsigned FULL = 0xffffffffu;
    const float* base = in + (size_t)b * (4 + NUM_CLASSES) * ANCHORS;

    // ---- Phase 1: decode + class argmax + conf mask -> smem (coalesced) ----
    for (int a = tid; a < PADDED; a += NT) {
        if (a < ANCHORS) {
            float xc = base[0 * ANCHORS + a];
            float yc = base[1 * ANCHORS + a];
            float w  = base[2 * ANCHORS + a];
            float h  = base[3 * ANCHORS + a];

            float bs = base[4 * ANCHORS + a];
            int   bc = 0;
            #pragma unroll
            for (int c = 1; c < NUM_CLASSES; c++) {
                float v = base[(4 + c) * ANCHORS + a];
                if (v > bs) { bs = v; bc = c; }   // strict > = first max (jnp.argmax)
            }

            float hw = w * 0.5f;
            float hh = h * 0.5f;
            float y1 = fminf(fmaxf(yc - hh, 0.0f), 1.0f);
            float x1 = fminf(fmaxf(xc - hw, 0.0f), 1.0f);
            float y2 = fminf(fmaxf(yc + hh, 0.0f), 1.0f);
            float x2 = fminf(fmaxf(xc + hw, 0.0f), 1.0f);

            sbox[a] = make_float4(y1, x1, y2, x2);
            ssc[a]  = (bs >= CONF) ? bs : -1.0f;
            scls[a] = (unsigned char)bc;
        } else {
            sbox[a] = make_float4(0.0f, 0.0f, 0.0f, 0.0f);
            ssc[a]  = -1.0f;
            scls[a] = 0;
        }
    }
    __syncthreads();

    // ---- Register-resident slice: thread t owns anchors [t*17, t*17+17) ----
    float ry1[KPT], rx1[KPT], ry2[KPT], rx2[KPT], rsc[KPT];
    int tkey = NEG_INF_I;   // float bits of best score, compared as s32
    int tbi  = 0;
    #pragma unroll
    for (int k = 0; k < KPT; k++) {
        int g = tid * KPT + k;
        float4 v = sbox[g];
        ry1[k] = v.x; rx1[k] = v.y; ry2[k] = v.z; rx2[k] = v.w;
        float sv = ssc[g];
        rsc[k] = sv;
        int ik = __float_as_int(sv);
        if (ik > tkey) { tkey = ik; tbi = g; }   // ascending k => first max
    }

    float* out_boxes = out + (size_t)b * MAX_DET * 4;
    float* out_cls   = out + (size_t)BATCH * MAX_DET * 4 + (size_t)b * MAX_DET;
    float* out_sc    = out + (size_t)BATCH * MAX_DET * 5 + (size_t)b * MAX_DET;
    float* out_nd    = out + (size_t)BATCH * MAX_DET * 6 + b;

    const int lane = tid & 31;
    const int wid  = tid >> 5;

    // ---- Phase 2: greedy NMS; 1 barrier/iter, redux-based argmax ----
    int ndet = 0;
    for (int it = 0; it < MAX_DET; it++) {
        const int p = it & 1;

        // warp winner: redux.max over int keys, lowest matching lane = smallest index
        int m = __reduce_max_sync(FULL, tkey);
        unsigned ball = __ballot_sync(FULL, tkey == m);
        int src = __ffs(ball) - 1;
        int wi  = __shfl_sync(FULL, tbi, src);
        if (lane == 0) { red_k[p][wid] = m; red_i[p][wid] = wi; }
        __syncthreads();

        // every warp redundantly reduces the 16 warp winners
        int k2 = (lane < NWARPS) ? red_k[p][lane] : NEG_INF_I;
        int i2 = (lane < NWARPS) ? red_i[p][lane] : 0;
        int m2 = __reduce_max_sync(FULL, k2);
        ball = __ballot_sync(FULL, k2 == m2);
        src  = __ffs(ball) - 1;
        int idx = __shfl_sync(FULL, i2, src);

        if (m2 < 0) break;                    // winner score is -1 => done (uniform)
        float s = __int_as_float(m2);
        float4 bb = sbox[idx];                // conflict-free broadcast LDS

        if (tid == 0) {
            out_boxes[it * 4 + 0] = bb.x;
            out_boxes[it * 4 + 1] = bb.y;
            out_boxes[it * 4 + 2] = bb.z;
            out_boxes[it * 4 + 3] = bb.w;
            out_cls[it] = (float)scls[idx];
            out_sc[it]  = s;
        }

        // fused suppression + next-winner scan (registers only)
        if (tkey > 0) {                       // thread fully dead -> skip, state stays exact
            float aa = (bb.z - bb.x) * (bb.w - bb.y);
            int nkey = NEG_INF_I; int nbi = 0;
            #pragma unroll
            for (int k = 0; k < KPT; k++) {
                int g = tid * KPT + k;
                float v = rsc[k];
                float iy1 = fmaxf(bb.x, ry1[k]);
                float ix1 = fmaxf(bb.y, rx1[k]);
                float iy2 = fminf(bb.z, ry2[k]);
                float ix2 = fminf(bb.w, rx2[k]);
                float dh  = fmaxf(iy2 - iy1, 0.0f);
                float dw  = fmaxf(ix2 - ix1, 0.0f);
                float inter = dh * dw;
                float ab  = (ry2[k] - ry1[k]) * (rx2[k] - rx1[k]);
                float uni = aa + ab - inter;
                // exact fl(inter/uni) > 0.45f, no division; uni==0 => d=0,t=0 => false,
                // so the uni>0 guard is provably redundant (inter <= min(aa,ab) under
                // monotone fp rounding).
                float d = fmaf(-IOU_C, uni, inter);
                bool sup = (d > uni * HC) || (g == idx);
                v = sup ? -1.0f : v;
                rsc[k] = v;
                int ik = __float_as_int(v);
                if (ik > nkey) { nkey = ik; nbi = g; }
            }
            tkey = nkey; tbi = nbi;
        }
        ndet++;
    }

    // tail zero-fill (reference emits zeros for !ok slots)
    for (int i = ndet + tid; i < MAX_DET; i += NT) {
        out_boxes[i * 4 + 0] = 0.0f;
        out_boxes[i * 4 + 1] = 0.0f;
        out_boxes[i * 4 + 2] = 0.0f;
        out_boxes[i * 4 + 3] = 0.0f;
        out_cls[i] = 0.0f;
        out_sc[i]  = 0.0f;
    }
    if (tid == 0) *out_nd = (float)ndet;
}

extern "C" void kernel_launch(void* const* d_in, const int* in_sizes, int n_in,
                              void* d_out, int out_size)
{
    (void)in_sizes; (void)n_in; (void)out_size;
    const float* in = (const float*)d_in[0];
    float* out = (float*)d_out;

    cudaFuncSetAttribute(yolo_nms_kernel,
                         cudaFuncAttributeMaxDynamicSharedMemorySize, SMEM_BYTES);
    yolo_nms_kernel<<<BATCH, NT, SMEM_BYTES>>>(in, out);
}

// round 4
// speedup vs baseline: 3.3844x; 1.0875x over previous
#include <cuda_runtime.h>

#define NUM_CLASSES 32
#define MAX_DET     100
#define CONF        0.25f
#define IOU_C       0.45f
#define HC          1.4901161193847656e-8f   // 2^-26 = half-ulp(0.45f)
#define BATCH       64
#define ANCHORS     8400
#define NT          256
#define KPT         34
#define PADDED      (NT * KPT)               // 8704
#define NWARPS      (NT / 32)                // 8
#define NEG_INF_I   ((int)0x80000000)

#define P1_NT       512
#define P1_GRIDX    (PADDED / P1_NT)         // 17

// scratch (allocation-free rule: __device__ globals)
__device__ float4 g_box[BATCH * PADDED];
__device__ float  g_sc [BATCH * PADDED];
__device__ float  g_cls[BATCH * PADDED];

// NMS smem: float4 boxes[8704] | float cls[8704]
#define SMEM_BYTES (PADDED * 16 + PADDED * 4)

// ---------------- Phase 1: full-chip decode ----------------
__global__ __launch_bounds__(P1_NT)
void decode_kernel(const float* __restrict__ in)
{
    const int a = blockIdx.x * P1_NT + threadIdx.x;   // 0..8703
    const int b = blockIdx.y;
    const size_t o = (size_t)b * PADDED + a;

    if (a < ANCHORS) {
        const float* base = in + (size_t)b * (4 + NUM_CLASSES) * ANCHORS;
        float xc = base[0 * ANCHORS + a];
        float yc = base[1 * ANCHORS + a];
        float w  = base[2 * ANCHORS + a];
        float h  = base[3 * ANCHORS + a];

        float bs = base[4 * ANCHORS + a];
        int   bc = 0;
        #pragma unroll
        for (int c = 1; c < NUM_CLASSES; c++) {
            float v = base[(4 + c) * ANCHORS + a];
            if (v > bs) { bs = v; bc = c; }   // strict > = first max (jnp.argmax)
        }

        float hw = w * 0.5f;
        float hh = h * 0.5f;
        float y1 = fminf(fmaxf(yc - hh, 0.0f), 1.0f);
        float x1 = fminf(fmaxf(xc - hw, 0.0f), 1.0f);
        float y2 = fminf(fmaxf(yc + hh, 0.0f), 1.0f);
        float x2 = fminf(fmaxf(xc + hw, 0.0f), 1.0f);

        g_box[o] = make_float4(y1, x1, y2, x2);
        g_sc[o]  = (bs >= CONF) ? bs : -1.0f;
        g_cls[o] = (float)bc;
    } else {
        g_box[o] = make_float4(0.0f, 0.0f, 0.0f, 0.0f);
        g_sc[o]  = -1.0f;
        g_cls[o] = 0.0f;
    }
}

// ---------------- Phase 2: per-image NMS with top-2 lookahead ----------------
__global__ __launch_bounds__(NT, 1)
void nms_kernel(float* __restrict__ out)
{
    extern __shared__ char smem[];
    float4* sbox = reinterpret_cast<float4*>(smem);
    float*  scls = reinterpret_cast<float*>(smem + PADDED * 16);

    __shared__ int red_k[2][2 * NWARPS];   // double-buffered warp top-2
    __shared__ int red_i[2][2 * NWARPS];

    const int b    = blockIdx.x;
    const int tid  = threadIdx.x;
    const int lane = tid & 31;
    const int wid  = tid >> 5;
    const unsigned FULL = 0xffffffffu;

    // coalesced smem fill
    const float4* gb = g_box + (size_t)b * PADDED;
    const float*  gc = g_cls + (size_t)b * PADDED;
    for (int a = tid; a < PADDED; a += NT) { sbox[a] = gb[a]; scls[a] = gc[a]; }
    __syncthreads();

    // register slice: thread t owns anchors [t*34, t*34+34)
    float ry1[KPT], rx1[KPT], ry2[KPT], rx2[KPT], rsc[KPT];
    const float* gs = g_sc + (size_t)b * PADDED + tid * KPT;
    int tk1 = NEG_INF_I, ti1 = 0, tk2 = NEG_INF_I, ti2 = 0;
    #pragma unroll
    for (int k = 0; k < KPT; k++) {
        float4 v = sbox[tid * KPT + k];
        ry1[k] = v.x; rx1[k] = v.y; ry2[k] = v.z; rx2[k] = v.w;
        float sv = gs[k];
        rsc[k] = sv;
        int ik = __float_as_int(sv);
        int g  = tid * KPT + k;
        if (ik > tk1)      { tk2 = tk1; ti2 = ti1; tk1 = ik; ti1 = g; }
        else if (ik > tk2) { tk2 = ik; ti2 = g; }
    }

    float* out_boxes = out + (size_t)b * MAX_DET * 4;
    float* out_cls   = out + (size_t)BATCH * MAX_DET * 4 + (size_t)b * MAX_DET;
    float* out_sc    = out + (size_t)BATCH * MAX_DET * 5 + (size_t)b * MAX_DET;
    float* out_nd    = out + (size_t)BATCH * MAX_DET * 6 + b;

    int ndet = 0;
    int p = 0;
    while (ndet < MAX_DET) {
        // ---- warp top-2 (redux + ballot; int keys are order-exact float bits) ----
        int m1 = __reduce_max_sync(FULL, tk1);
        unsigned ball = __ballot_sync(FULL, tk1 == m1);
        int src = __ffs(ball) - 1;                       // lowest lane = smallest index
        int wi1 = __shfl_sync(FULL, ti1, src);
        int kx = (lane == src) ? tk2 : tk1;              // remove winner, expose its 2nd
        int ix = (lane == src) ? ti2 : ti1;
        int m2w = __reduce_max_sync(FULL, kx);
        ball = __ballot_sync(FULL, kx == m2w);
        src  = __ffs(ball) - 1;
        int wi2 = __shfl_sync(FULL, ix, src);
        if (lane == 0) {
            red_k[p][2 * wid]     = m1;  red_i[p][2 * wid]     = wi1;
            red_k[p][2 * wid + 1] = m2w; red_i[p][2 * wid + 1] = wi2;
        }
        __syncthreads();

        // ---- block top-2 over 16 entries (every warp, redundantly) ----
        int ek = (lane < 2 * NWARPS) ? red_k[p][lane] : NEG_INF_I;
        int ei = (lane < 2 * NWARPS) ? red_i[p][lane] : 0;
        int M1 = __reduce_max_sync(FULL, ek);
        ball = __ballot_sync(FULL, ek == M1);
        src  = __ffs(ball) - 1;
        int I1 = __shfl_sync(FULL, ei, src);
        int ekx = (lane == src) ? NEG_INF_I : ek;
        int M2 = __reduce_max_sync(FULL, ekx);
        ball = __ballot_sync(FULL, ekx == M2);
        int src2 = __ffs(ball) - 1;
        int I2 = __shfl_sync(FULL, ei, src2);

        if (M1 < 0) break;                                // no live score left
        float4 bb1 = sbox[I1];
        float  aa1 = (bb1.z - bb1.x) * (bb1.w - bb1.y);

        // lookahead: is the global 2nd-best the next reference winner?
        bool two = false;
        float4 bb2 = bb1;
        float  aa2 = 0.0f;
        if (M2 >= 0 && ndet + 1 < MAX_DET) {
            bb2 = sbox[I2];
            float iy1 = fmaxf(bb1.x, bb2.x);
            float ixa = fmaxf(bb1.y, bb2.y);
            float iy2 = fminf(bb1.z, bb2.z);
            float ixb = fminf(bb1.w, bb2.w);
            float inter = fmaxf(iy2 - iy1, 0.0f) * fmaxf(ixb - ixa, 0.0f);
            float ab  = (bb2.z - bb2.x) * (bb2.w - bb2.y);
            float uni = aa1 + ab - inter;
            float d   = fmaf(-IOU_C, uni, inter);
            two = !(d > uni * HC);                        // survives winner1's pass
            aa2 = ab;
        }

        if (tid == 0) {
            out_boxes[ndet * 4 + 0] = bb1.x;
            out_boxes[ndet * 4 + 1] = bb1.y;
            out_boxes[ndet * 4 + 2] = bb1.z;
            out_boxes[ndet * 4 + 3] = bb1.w;
            out_cls[ndet] = scls[I1];
            out_sc[ndet]  = __int_as_float(M1);
            if (two) {
                out_boxes[(ndet + 1) * 4 + 0] = bb2.x;
                out_boxes[(ndet + 1) * 4 + 1] = bb2.y;
                out_boxes[(ndet + 1) * 4 + 2] = bb2.z;
                out_boxes[(ndet + 1) * 4 + 3] = bb2.w;
                out_cls[ndet + 1] = scls[I2];
                out_sc[ndet + 1]  = __int_as_float(M2);
            }
        }

        // ---- fused suppression + next top-2 scan (registers only) ----
        if (tk1 > 0) {                        // whole slice dead -> state stays exact
            int nk1 = NEG_INF_I, ni1 = 0, nk2 = NEG_INF_I, ni2 = 0;
            if (two) {
                #pragma unroll
                for (int k = 0; k < KPT; k++) {
                    int g = tid * KPT + k;
                    float v = rsc[k];
                    float ab = (ry2[k] - ry1[k]) * (rx2[k] - rx1[k]);
                    // IoU vs winner1
                    float a1 = fmaxf(bb1.x, ry1[k]);
                    float b1v= fmaxf(bb1.y, rx1[k]);
                    float c1 = fminf(bb1.z, ry2[k]);
                    float d1v= fminf(bb1.w, rx2[k]);
                    float in1 = fmaxf(c1 - a1, 0.0f) * fmaxf(d1v - b1v, 0.0f);
                    float u1  = aa1 + ab - in1;
                    float e1  = fmaf(-IOU_C, u1, in1);
                    bool s1 = (e1 > u1 * HC) || (g == I1);
                    // IoU vs winner2
                    float a2 = fmaxf(bb2.x, ry1[k]);
                    float b2v= fmaxf(bb2.y, rx1[k]);
                    float c2 = fminf(bb2.z, ry2[k]);
                    float d2v= fminf(bb2.w, rx2[k]);
                    float in2 = fmaxf(c2 - a2, 0.0f) * fmaxf(d2v - b2v, 0.0f);
                    float u2  = aa2 + ab - in2;
                    float e2  = fmaf(-IOU_C, u2, in2);
                    bool s2 = (e2 > u2 * HC) || (g == I2);
                    v = (s1 || s2) ? -1.0f : v;
                    rsc[k] = v;
                    int ik = __float_as_int(v);
                    if (ik > nk1)      { nk2 = nk1; ni2 = ni1; nk1 = ik; ni1 = g; }
                    else if (ik > nk2) { nk2 = ik; ni2 = g; }
                }
            } else {
                #pragma unroll
                for (int k = 0; k < KPT; k++) {
                    int g = tid * KPT + k;
                    float v = rsc[k];
                    float ab = (ry2[k] - ry1[k]) * (rx2[k] - rx1[k]);
                    float a1 = fmaxf(bb1.x, ry1[k]);
                    float b1v= fmaxf(bb1.y, rx1[k]);
                    float c1 = fminf(bb1.z, ry2[k]);
                    float d1v= fminf(bb1.w, rx2[k]);
                    float in1 = fmaxf(c1 - a1, 0.0f) * fmaxf(d1v - b1v, 0.0f);
                    float u1  = aa1 + ab - in1;
                    float e1  = fmaf(-IOU_C, u1, in1);
                    bool s1 = (e1 > u1 * HC) || (g == I1);
                    v = s1 ? -1.0f : v;
                    rsc[k] = v;
                    int ik = __float_as_int(v);
                    if (ik > nk1)      { nk2 = nk1; ni2 = ni1; nk1 = ik; ni1 = g; }
                    else if (ik > nk2) { nk2 = ik; ni2 = g; }
                }
            }
            tk1 = nk1; ti1 = ni1; tk2 = nk2; ti2 = ni2;
        }

        ndet += two ? 2 : 1;
        p ^= 1;
    }

    // tail zero-fill (out is poisoned; reference emits zeros for !ok slots)
    for (int i = ndet + tid; i < MAX_DET; i += NT) {
        out_boxes[i * 4 + 0] = 0.0f;
        out_boxes[i * 4 + 1] = 0.0f;
        out_boxes[i * 4 + 2] = 0.0f;
        out_boxes[i * 4 + 3] = 0.0f;
        out_cls[i] = 0.0f;
        out_sc[i]  = 0.0f;
    }
    if (tid == 0) *out_nd = (float)ndet;
}

extern "C" void kernel_launch(void* const* d_in, const int* in_sizes, int n_in,
                              void* d_out, int out_size)
{
    (void)in_sizes; (void)n_in; (void)out_size;
    const float* in = (const float*)d_in[0];
    float* out = (float*)d_out;

    cudaFuncSetAttribute(nms_kernel,
                         cudaFuncAttributeMaxDynamicSharedMemorySize, SMEM_BYTES);

    dim3 g1(P1_GRIDX, BATCH);
    decode_kernel<<<g1, P1_NT>>>(in);
    nms_kernel<<<BATCH, NT, SMEM_BYTES>>>(out);
}

// round 5
// speedup vs baseline: 3.6729x; 1.0852x over previous
#include <cuda_runtime.h>

#define NUM_CLASSES 32
#define MAX_DET     100
#define CONF        0.25f
#define IOU_C       0.45f
#define HC          1.4901161193847656e-8f   // 2^-26 = half-ulp(0.45f)
#define BATCH       64
#define ANCHORS     8400
#define NT          384
#define KPT         23
#define PADDED      (NT * KPT)               // 8832
#define NWARPS      (NT / 32)                // 12
#define NEG_INF_I   ((int)0x80000000)

#define P1_NT       512
#define P1_GRIDX    ((PADDED + P1_NT - 1) / P1_NT)   // 18

// scratch (allocation-free rule: __device__ globals)
__device__ float4 g_box[BATCH * PADDED];
__device__ float  g_sc [BATCH * PADDED];
__device__ float  g_cls[BATCH * PADDED];

// NMS smem: float4 boxes[8832] | float cls[8832]
#define SMEM_BYTES (PADDED * 16 + PADDED * 4)

// ---------------- Phase 1: full-chip decode ----------------
__global__ __launch_bounds__(P1_NT)
void decode_kernel(const float* __restrict__ in)
{
    const int a = blockIdx.x * P1_NT + threadIdx.x;
    const int b = blockIdx.y;
    if (a >= PADDED) return;
    const size_t o = (size_t)b * PADDED + a;

    if (a < ANCHORS) {
        const float* base = in + (size_t)b * (4 + NUM_CLASSES) * ANCHORS;
        float xc = base[0 * ANCHORS + a];
        float yc = base[1 * ANCHORS + a];
        float w  = base[2 * ANCHORS + a];
        float h  = base[3 * ANCHORS + a];

        float bs = base[4 * ANCHORS + a];
        int   bc = 0;
        #pragma unroll
        for (int c = 1; c < NUM_CLASSES; c++) {
            float v = base[(4 + c) * ANCHORS + a];
            if (v > bs) { bs = v; bc = c; }   // strict > = first max (jnp.argmax)
        }

        float hw = w * 0.5f;
        float hh = h * 0.5f;
        float y1 = fminf(fmaxf(yc - hh, 0.0f), 1.0f);
        float x1 = fminf(fmaxf(xc - hw, 0.0f), 1.0f);
        float y2 = fminf(fmaxf(yc + hh, 0.0f), 1.0f);
        float x2 = fminf(fmaxf(xc + hw, 0.0f), 1.0f);

        g_box[o] = make_float4(y1, x1, y2, x2);
        g_sc[o]  = (bs >= CONF) ? bs : -1.0f;
        g_cls[o] = (float)bc;
    } else {
        g_box[o] = make_float4(0.0f, 0.0f, 0.0f, 0.0f);
        g_sc[o]  = -1.0f;
        g_cls[o] = 0.0f;
    }
}

// suppression scan + next top-2 (TWO/CHECK are literal 0/1 -> dead-code elim)
#define SCAN_BODY(TWO, CHECK)                                                  \
{                                                                              \
    int nk1 = NEG_INF_I, ni1 = 0, nk2 = NEG_INF_I, ni2 = 0;                    \
    _Pragma("unroll")                                                          \
    for (int k = 0; k < KPT; k++) {                                            \
        int g = tid * KPT + k;                                                 \
        float v = rsc[k];                                                      \
        float ab = (ry2[k] - ry1[k]) * (rx2[k] - rx1[k]);                      \
        float a1 = fmaxf(bb1.x, ry1[k]);                                       \
        float b1v= fmaxf(bb1.y, rx1[k]);                                       \
        float c1 = fminf(bb1.z, ry2[k]);                                       \
        float d1v= fminf(bb1.w, rx2[k]);                                       \
        float in1 = fmaxf(c1 - a1, 0.0f) * fmaxf(d1v - b1v, 0.0f);             \
        float u1  = aa1 + ab - in1;                                            \
        float e1  = fmaf(-IOU_C, u1, in1);                                     \
        bool sup = (e1 > u1 * HC);                                             \
        if (CHECK) sup = sup || (g == I1);                                     \
        if (TWO) {                                                             \
            float a2 = fmaxf(bb2.x, ry1[k]);                                   \
            float b2v= fmaxf(bb2.y, rx1[k]);                                   \
            float c2 = fminf(bb2.z, ry2[k]);                                   \
            float d2v= fminf(bb2.w, rx2[k]);                                   \
            float in2 = fmaxf(c2 - a2, 0.0f) * fmaxf(d2v - b2v, 0.0f);         \
            float u2  = aa2 + ab - in2;                                        \
            float e2  = fmaf(-IOU_C, u2, in2);                                 \
            bool s2 = (e2 > u2 * HC);                                          \
            if (CHECK) s2 = s2 || (g == I2);                                   \
            sup = sup || s2;                                                   \
        }                                                                      \
        v = sup ? -1.0f : v;                                                   \
        rsc[k] = v;                                                            \
        int ik = __float_as_int(v);                                            \
        if (ik > nk1)      { nk2 = nk1; ni2 = ni1; nk1 = ik; ni1 = g; }        \
        else if (ik > nk2) { nk2 = ik; ni2 = g; }                              \
    }                                                                          \
    tk1 = nk1; ti1 = ni1; tk2 = nk2; ti2 = ni2;                                \
}

// ---------------- Phase 2: per-image NMS with top-2 lookahead ----------------
__global__ __launch_bounds__(NT, 1)
void nms_kernel(float* __restrict__ out)
{
    extern __shared__ char smem[];
    float4* sbox = reinterpret_cast<float4*>(smem);
    float*  scls = reinterpret_cast<float*>(smem + PADDED * 16);

    __shared__ int red_k[2][2 * NWARPS];   // double-buffered warp top-2
    __shared__ int red_i[2][2 * NWARPS];

    const int b    = blockIdx.x;
    const int tid  = threadIdx.x;
    const int lane = tid & 31;
    const int wid  = tid >> 5;
    const unsigned FULL = 0xffffffffu;

    // coalesced smem fill
    const float4* gb = g_box + (size_t)b * PADDED;
    const float*  gc = g_cls + (size_t)b * PADDED;
    for (int a = tid; a < PADDED; a += NT) { sbox[a] = gb[a]; scls[a] = gc[a]; }
    __syncthreads();

    // register slice: thread t owns anchors [t*23, t*23+23)
    float ry1[KPT], rx1[KPT], ry2[KPT], rx2[KPT], rsc[KPT];
    const float* gs = g_sc + (size_t)b * PADDED + tid * KPT;
    int tk1 = NEG_INF_I, ti1 = 0, tk2 = NEG_INF_I, ti2 = 0;
    #pragma unroll
    for (int k = 0; k < KPT; k++) {
        int g = tid * KPT + k;
        float4 v = sbox[g];
        ry1[k] = v.x; rx1[k] = v.y; ry2[k] = v.z; rx2[k] = v.w;
        float sv = gs[k];
        rsc[k] = sv;
        int ik = __float_as_int(sv);
        if (ik > tk1)      { tk2 = tk1; ti2 = ti1; tk1 = ik; ti1 = g; }
        else if (ik > tk2) { tk2 = ik; ti2 = g; }
    }

    float* out_boxes = out + (size_t)b * MAX_DET * 4;
    float* out_cls   = out + (size_t)BATCH * MAX_DET * 4 + (size_t)b * MAX_DET;
    float* out_sc    = out + (size_t)BATCH * MAX_DET * 5 + (size_t)b * MAX_DET;
    float* out_nd    = out + (size_t)BATCH * MAX_DET * 6 + b;

    int ndet = 0;
    int p = 0;
    while (ndet < MAX_DET) {
        // ---- warp top-2 (redux + ballot; int keys order-exact for our score set) ----
        int m1 = __reduce_max_sync(FULL, tk1);
        unsigned ball = __ballot_sync(FULL, tk1 == m1);
        int src = __ffs(ball) - 1;                       // lowest lane = smallest index
        int wi1 = __shfl_sync(FULL, ti1, src);
        int kx = (lane == src) ? tk2 : tk1;              // remove winner, expose its 2nd
        int ix = (lane == src) ? ti2 : ti1;
        int m2w = __reduce_max_sync(FULL, kx);
        ball = __ballot_sync(FULL, kx == m2w);
        src  = __ffs(ball) - 1;
        int wi2 = __shfl_sync(FULL, ix, src);
        if (lane == 0) {
            red_k[p][2 * wid]     = m1;  red_i[p][2 * wid]     = wi1;
            red_k[p][2 * wid + 1] = m2w; red_i[p][2 * wid + 1] = wi2;
        }
        __syncthreads();

        // ---- block top-2 over 24 entries (every warp, redundantly) ----
        int ek = (lane < 2 * NWARPS) ? red_k[p][lane] : NEG_INF_I;
        int ei = (lane < 2 * NWARPS) ? red_i[p][lane] : 0;
        int M1 = __reduce_max_sync(FULL, ek);
        ball = __ballot_sync(FULL, ek == M1);
        src  = __ffs(ball) - 1;
        int I1 = __shfl_sync(FULL, ei, src);
        int ekx = (lane == src) ? NEG_INF_I : ek;
        int M2 = __reduce_max_sync(FULL, ekx);
        ball = __ballot_sync(FULL, ekx == M2);
        int src2 = __ffs(ball) - 1;
        int I2 = __shfl_sync(FULL, ei, src2);

        if (M1 < 0) break;                                // no live score left
        float4 bb1 = sbox[I1];
        float  aa1 = (bb1.z - bb1.x) * (bb1.w - bb1.y);

        // lookahead: is the global 2nd-best the next reference winner?
        bool two = false;
        float4 bb2 = bb1;
        float  aa2 = 0.0f;
        if (M2 >= 0 && ndet + 1 < MAX_DET) {
            bb2 = sbox[I2];
            float iy1 = fmaxf(bb1.x, bb2.x);
            float ixa = fmaxf(bb1.y, bb2.y);
            float iy2 = fminf(bb1.z, bb2.z);
            float ixb = fminf(bb1.w, bb2.w);
            float inter = fmaxf(iy2 - iy1, 0.0f) * fmaxf(ixb - ixa, 0.0f);
            float ab  = (bb2.z - bb2.x) * (bb2.w - bb2.y);
            float uni = aa1 + ab - inter;
            float d   = fmaf(-IOU_C, uni, inter);
            two = !(d > uni * HC);                        // survives winner1's pass
            aa2 = ab;
        }

        if (tid == 0) {
            out_boxes[ndet * 4 + 0] = bb1.x;
            out_boxes[ndet * 4 + 1] = bb1.y;
            out_boxes[ndet * 4 + 2] = bb1.z;
            out_boxes[ndet * 4 + 3] = bb1.w;
            out_cls[ndet] = scls[I1];
            out_sc[ndet]  = __int_as_float(M1);
            if (two) {
                out_boxes[(ndet + 1) * 4 + 0] = bb2.x;
                out_boxes[(ndet + 1) * 4 + 1] = bb2.y;
                out_boxes[(ndet + 1) * 4 + 2] = bb2.z;
                out_boxes[(ndet + 1) * 4 + 3] = bb2.w;
                out_cls[ndet + 1] = scls[I2];
                out_sc[ndet + 1]  = __int_as_float(M2);
            }
        }

        // ---- fused suppression + next top-2 scan ----
        // Fast path: winners with positive area self-suppress via their own IoU
        // test (in == ab == aa exactly => e = 0.55*aa > aa*2^-26), so the
        // per-element index checks are dropped. Slow path keeps them.
        bool bothpos = (aa1 > 0.0f) && (!two || aa2 > 0.0f);   // uniform
        if (tk1 > 0) {                        // whole slice dead -> state stays exact
            if (bothpos) {
                if (two) SCAN_BODY(1, 0) else SCAN_BODY(0, 0)
            } else {
                if (two) SCAN_BODY(1, 1) else SCAN_BODY(0, 1)
            }
        }

        ndet += two ? 2 : 1;
        p ^= 1;
    }

    // tail zero-fill (out is poisoned; reference emits zeros for !ok slots)
    for (int i = ndet + tid; i < MAX_DET; i += NT) {
        out_boxes[i * 4 + 0] = 0.0f;
        out_boxes[i * 4 + 1] = 0.0f;
        out_boxes[i * 4 + 2] = 0.0f;
        out_boxes[i * 4 + 3] = 0.0f;
        out_cls[i] = 0.0f;
        out_sc[i]  = 0.0f;
    }
    if (tid == 0) *out_nd = (float)ndet;
}

extern "C" void kernel_launch(void* const* d_in, const int* in_sizes, int n_in,
                              void* d_out, int out_size)
{
    (void)in_sizes; (void)n_in; (void)out_size;
    const float* in = (const float*)d_in[0];
    float* out = (float*)d_out;

    cudaFuncSetAttribute(nms_kernel,
                         cudaFuncAttributeMaxDynamicSharedMemorySize, SMEM_BYTES);

    dim3 g1(P1_GRIDX, BATCH);
    decode_kernel<<<g1, P1_NT>>>(in);
    nms_kernel<<<BATCH, NT, SMEM_BYTES>>>(out);
}

// round 6
// speedup vs baseline: 3.7793x; 1.0290x over previous
#include <cuda_runtime.h>
#include <cstdint>

#define NUM_CLASSES 32
#define MAX_DET     100
#define CONF        0.25f
#define IOU_C       0.45f
#define HC          1.4901161193847656e-8f   // 2^-26 = half-ulp(0.45f)
#define BATCH       64
#define ANCHORS     8400
#define NT          384
#define KPT         12
#define HALF        (NT * KPT)               // 4608 anchors per CTA
#define PADDED      (2 * HALF)               // 9216
#define NWARPS      (NT / 32)                // 12
#define NEG_INF_I   ((int)0x80000000)

#define P1_NT       512
#define P1_GRIDX    (PADDED / P1_NT)         // 18

// scratch (allocation-free rule: __device__ globals)
__device__ float4 g_box[BATCH * PADDED];
__device__ float  g_sc [BATCH * PADDED];
__device__ float  g_cls[BATCH * PADDED];

// NMS dynamic smem per CTA: float4 boxes[4608] | float cls[4608]
#define SMEM_BYTES (HALF * 16 + HALF * 4)

// ---------------- cluster / mbarrier helpers (compile-safe base forms) ----------------
__device__ __forceinline__ uint32_t smem_u32(const void* p) {
    uint32_t a;
    asm("{ .reg .u64 t; cvta.to.shared.u64 t, %1; cvt.u32.u64 %0, t; }" : "=r"(a) : "l"(p));
    return a;
}
__device__ __forceinline__ uint32_t mapa_peer(uint32_t laddr, uint32_t peer) {
    uint32_t r;
    asm("mapa.shared::cluster.u32 %0, %1, %2;" : "=r"(r) : "r"(laddr), "r"(peer));
    return r;
}
__device__ __forceinline__ void st_peer_u32(uint32_t raddr, uint32_t v) {
    asm volatile("st.shared::cluster.u32 [%0], %1;" :: "r"(raddr), "r"(v) : "memory");
}
__device__ __forceinline__ void fence_cluster() {
    asm volatile("fence.acq_rel.cluster;" ::: "memory");
}
__device__ __forceinline__ void mbar_init(uint32_t a, uint32_t cnt) {
    asm volatile("mbarrier.init.shared.b64 [%0], %1;" :: "r"(a), "r"(cnt) : "memory");
}
__device__ __forceinline__ void mbar_arrive_peer(uint32_t laddr, uint32_t peer) {
    asm volatile("{\n\t.reg .b32 r;\n\t"
                 "mapa.shared::cluster.u32 r, %0, %1;\n\t"
                 "mbarrier.arrive.shared::cluster.b64 _, [r];\n\t}"
                 :: "r"(laddr), "r"(peer) : "memory");
}
__device__ __forceinline__ void mbar_wait(uint32_t a, uint32_t parity) {
    uint32_t done;
    asm volatile("{\n\t.reg .pred p;\n\t"
                 "mbarrier.try_wait.parity.shared::cta.b64 p, [%1], %2;\n\t"
                 "selp.b32 %0, 1, 0, p;\n\t}"
                 : "=r"(done) : "r"(a), "r"(parity) : "memory");
    if (!done) {
        asm volatile("{\n\t.reg .pred P1;\n\t"
                     "WL_%=:\n\t"
                     "mbarrier.try_wait.parity.shared::cta.b64 P1, [%0], %1;\n\t"
                     "@P1 bra.uni WD_%=;\n\t"
                     "bra.uni WL_%=;\n\t"
                     "WD_%=:\n\t}"
                     :: "r"(a), "r"(parity) : "memory");
    }
}
#define CLUSTER_ARRIVE() asm volatile("barrier.cluster.arrive.aligned;" ::: "memory")
#define CLUSTER_WAIT()   asm volatile("barrier.cluster.wait.aligned;" ::: "memory")

// ---------------- Phase 1: full-chip decode ----------------
__global__ __launch_bounds__(P1_NT)
void decode_kernel(const float* __restrict__ in)
{
    const int a = blockIdx.x * P1_NT + threadIdx.x;   // 0..9215
    const int b = blockIdx.y;
    const size_t o = (size_t)b * PADDED + a;

    if (a < ANCHORS) {
        const float* base = in + (size_t)b * (4 + NUM_CLASSES) * ANCHORS;
        float xc = base[0 * ANCHORS + a];
        float yc = base[1 * ANCHORS + a];
        float w  = base[2 * ANCHORS + a];
        float h  = base[3 * ANCHORS + a];

        float bs = base[4 * ANCHORS + a];
        int   bc = 0;
        #pragma unroll
        for (int c = 1; c < NUM_CLASSES; c++) {
            float v = base[(4 + c) * ANCHORS + a];
            if (v > bs) { bs = v; bc = c; }   // strict > = first max (jnp.argmax)
        }

        float hw = w * 0.5f;
        float hh = h * 0.5f;
        float y1 = fminf(fmaxf(yc - hh, 0.0f), 1.0f);
        float x1 = fminf(fmaxf(xc - hw, 0.0f), 1.0f);
        float y2 = fminf(fmaxf(yc + hh, 0.0f), 1.0f);
        float x2 = fminf(fmaxf(xc + hw, 0.0f), 1.0f);

        g_box[o] = make_float4(y1, x1, y2, x2);
        g_sc[o]  = (bs >= CONF) ? bs : -1.0f;
        g_cls[o] = (float)bc;
    } else {
        g_box[o] = make_float4(0.0f, 0.0f, 0.0f, 0.0f);
        g_sc[o]  = -1.0f;
        g_cls[o] = 0.0f;
    }
}

// suppression scan + next top-2 (TWO/CHECK literal 0/1 -> dead-code elim)
#define SCAN_BODY(TWO, CHECK)                                                  \
{                                                                              \
    int nk1 = NEG_INF_I, ni1 = 0, nk2 = NEG_INF_I, ni2 = 0;                    \
    _Pragma("unroll")                                                          \
    for (int k = 0; k < KPT; k++) {                                            \
        float v = rsc[k];                                                      \
        float ab = rab[k];   /* bit-identical to per-iter recompute */         \
        float a1 = fmaxf(bb1.x, ry1[k]);                                       \
        float b1v= fmaxf(bb1.y, rx1[k]);                                       \
        float c1 = fminf(bb1.z, ry2[k]);                                       \
        float d1v= fminf(bb1.w, rx2[k]);                                       \
        float in1 = fmaxf(c1 - a1, 0.0f) * fmaxf(d1v - b1v, 0.0f);             \
        float u1  = aa1 + ab - in1;                                            \
        float e1  = fmaf(-IOU_C, u1, in1);                                     \
        bool sup = (e1 > u1 * HC);                                             \
        if (CHECK) sup = sup || (gbase + k == I1);                             \
        if (TWO) {                                                             \
            float a2 = fmaxf(bb2.x, ry1[k]);                                   \
            float b2v= fmaxf(bb2.y, rx1[k]);                                   \
            float c2 = fminf(bb2.z, ry2[k]);                                   \
            float d2v= fminf(bb2.w, rx2[k]);                                   \
            float in2 = fmaxf(c2 - a2, 0.0f) * fmaxf(d2v - b2v, 0.0f);         \
            float u2  = aa2 + ab - in2;                                        \
            float e2  = fmaf(-IOU_C, u2, in2);                                 \
            bool s2 = (e2 > u2 * HC);                                          \
            if (CHECK) s2 = s2 || (gbase + k == I2);                           \
            sup = sup || s2;                                                   \
        }                                                                      \
        v = sup ? -1.0f : v;                                                   \
        rsc[k] = v;                                                            \
        int ik = __float_as_int(v);                                            \
        if (ik > nk1)      { nk2 = nk1; ni2 = ni1; nk1 = ik; ni1 = tid*KPT+k; }\
        else if (ik > nk2) { nk2 = ik; ni2 = tid*KPT+k; }                      \
    }                                                                          \
    tk1 = nk1; ti1 = ni1; tk2 = nk2; ti2 = ni2;                                \
}

// ---------------- Phase 2: 2-CTA-cluster NMS with top-2 lookahead ----------------
__global__ __launch_bounds__(NT, 1) __cluster_dims__(2, 1, 1)
void nms_kernel(float* __restrict__ out)
{
    extern __shared__ char smem[];
    float4* sbox = reinterpret_cast<float4*>(smem);
    float*  scls = reinterpret_cast<float*>(smem + HALF * 16);

    __shared__ int red_k[2][2 * NWARPS];     // double-buffered warp top-2
    __shared__ int red_i[2][2 * NWARPS];
    __shared__ float    s_mail[2][16];       // [parity][2 cands x 8 words], peer-written
    __shared__ uint64_t s_mbar[2];

    const int tid  = threadIdx.x;
    const int lane = tid & 31;
    const int wid  = tid >> 5;
    const unsigned FULL = 0xffffffffu;
    uint32_t rank;
    asm("mov.u32 %0, %%cluster_ctarank;" : "=r"(rank));
    const uint32_t peer = rank ^ 1;
    const int b = blockIdx.x >> 1;

    const uint32_t mb0   = smem_u32(&s_mbar[0]);
    const uint32_t mb1   = smem_u32(&s_mbar[1]);
    const uint32_t mail0 = smem_u32(&s_mail[0][0]);
    const uint32_t mail1 = smem_u32(&s_mail[1][0]);

    if (tid == 0) { mbar_init(mb0, 1); mbar_init(mb1, 1); }

    // coalesced fill of own half
    const size_t gb0 = (size_t)b * PADDED + (size_t)rank * HALF;
    const float4* gb = g_box + gb0;
    const float*  gc = g_cls + gb0;
    for (int a = tid; a < HALF; a += NT) { sbox[a] = gb[a]; scls[a] = gc[a]; }
    __syncthreads();

    CLUSTER_ARRIVE(); CLUSTER_WAIT();        // mbarrier init visible cluster-wide

    // register slice: thread t owns local anchors [t*12, t*12+12)
    float ry1[KPT], rx1[KPT], ry2[KPT], rx2[KPT], rsc[KPT], rab[KPT];
    const float* gs = g_sc + gb0 + tid * KPT;
    const int gbase = (int)rank * HALF + tid * KPT;   // global anchor base
    int tk1 = NEG_INF_I, ti1 = 0, tk2 = NEG_INF_I, ti2 = 0;
    #pragma unroll
    for (int k = 0; k < KPT; k++) {
        float4 v = sbox[tid * KPT + k];
        ry1[k] = v.x; rx1[k] = v.y; ry2[k] = v.z; rx2[k] = v.w;
        rab[k] = (v.z - v.x) * (v.w - v.y);
        float sv = gs[k];
        rsc[k] = sv;
        int ik = __float_as_int(sv);
        if (ik > tk1)      { tk2 = tk1; ti2 = ti1; tk1 = ik; ti1 = tid*KPT+k; }
        else if (ik > tk2) { tk2 = ik; ti2 = tid*KPT+k; }
    }

    float* out_boxes = out + (size_t)b * MAX_DET * 4;
    float* out_cls   = out + (size_t)BATCH * MAX_DET * 4 + (size_t)b * MAX_DET;
    float* out_sc    = out + (size_t)BATCH * MAX_DET * 5 + (size_t)b * MAX_DET;
    float* out_nd    = out + (size_t)BATCH * MAX_DET * 6 + b;

    int ndet = 0, p = 0, ph0 = 0, ph1 = 0;
    while (ndet < MAX_DET) {
        // ---- warp top-2 over local indices (redux + ballot) ----
        int m1 = __reduce_max_sync(FULL, tk1);
        unsigned ball = __ballot_sync(FULL, tk1 == m1);
        int src = __ffs(ball) - 1;                       // lowest lane = smallest index
        int wi1 = __shfl_sync(FULL, ti1, src);
        int kx = (lane == src) ? tk2 : tk1;
        int ix = (lane == src) ? ti2 : ti1;
        int m2w = __reduce_max_sync(FULL, kx);
        ball = __ballot_sync(FULL, kx == m2w);
        src  = __ffs(ball) - 1;
        int wi2 = __shfl_sync(FULL, ix, src);
        if (lane == 0) {
            red_k[p][2 * wid]     = m1;  red_i[p][2 * wid]     = wi1;
            red_k[p][2 * wid + 1] = m2w; red_i[p][2 * wid + 1] = wi2;
        }
        __syncthreads();

        // ---- CTA top-2 over 24 entries (every warp, redundantly) ----
        int ek = (lane < 2 * NWARPS) ? red_k[p][lane] : NEG_INF_I;
        int ei = (lane < 2 * NWARPS) ? red_i[p][lane] : 0;
        int cm1 = __reduce_max_sync(FULL, ek);
        ball = __ballot_sync(FULL, ek == cm1);
        src  = __ffs(ball) - 1;
        int cl1 = __shfl_sync(FULL, ei, src);            // CTA-local idx of 1st
        int ekx = (lane == src) ? NEG_INF_I : ek;
        int cm2 = __reduce_max_sync(FULL, ekx);
        ball = __ballot_sync(FULL, ekx == cm2);
        int src2 = __ffs(ball) - 1;
        int cl2 = __shfl_sync(FULL, ei, src2);

        // ---- exchange CTA top-2 with peer (DSMEM mailbox + mbarrier) ----
        // Parity double-buffer: rewriting mail[p] at pass t is safe because our
        // wait on mbar[p^1] at pass t-1 required the peer's arrive, which is
        // program-ordered after the peer's pass t-2 reads of its mail[p].
        uint32_t mail = p ? mail1 : mail0;
        uint32_t mb   = p ? mb1   : mb0;
        if (tid == 0) {
            float4 bo1 = sbox[cl1]; float co1 = scls[cl1];
            float4 bo2 = sbox[cl2]; float co2 = scls[cl2];
            uint32_t r = mapa_peer(mail, peer);
            st_peer_u32(r +  0, (uint32_t)cm1);
            st_peer_u32(r +  4, (uint32_t)((int)rank * HALF + cl1));
            st_peer_u32(r +  8, __float_as_uint(bo1.x));
            st_peer_u32(r + 12, __float_as_uint(bo1.y));
            st_peer_u32(r + 16, __float_as_uint(bo1.z));
            st_peer_u32(r + 20, __float_as_uint(bo1.w));
            st_peer_u32(r + 24, __float_as_uint(co1));
            st_peer_u32(r + 32, (uint32_t)cm2);
            st_peer_u32(r + 36, (uint32_t)((int)rank * HALF + cl2));
            st_peer_u32(r + 40, __float_as_uint(bo2.x));
            st_peer_u32(r + 44, __float_as_uint(bo2.y));
            st_peer_u32(r + 48, __float_as_uint(bo2.z));
            st_peer_u32(r + 52, __float_as_uint(bo2.w));
            st_peer_u32(r + 56, __float_as_uint(co2));
            fence_cluster();                 // release the mailbox writes
            mbar_arrive_peer(mb, peer);
        }

        mbar_wait(mb, (uint32_t)(p ? ph1 : ph0));
        fence_cluster();                     // acquire peer's mailbox writes
        if (p) ph1 ^= 1; else ph0 ^= 1;

        // ---- symmetric merge of {own top-2} U {peer top-2} ----
        const float* M = s_mail[p];
        int pk1 = __float_as_int(M[0]);
        int pi1 = __float_as_int(M[1]);
        int pk2 = __float_as_int(M[8]);
        int pi2 = __float_as_int(M[9]);
        int og1 = (int)rank * HALF + cl1;
        int og2 = (int)rank * HALF + cl2;

        bool ow = (cm1 > pk1) || (cm1 == pk1 && og1 < pi1);
        int M1 = ow ? cm1 : pk1;
        int I1 = ow ? og1 : pi1;
        if (M1 < 0) break;                   // identical in both CTAs -> uniform

        float4 bb1; float cls1;
        if (ow) { bb1 = sbox[cl1]; cls1 = scls[cl1]; }
        else    { bb1 = make_float4(M[2], M[3], M[4], M[5]); cls1 = M[6]; }

        int ks  = ow ? cm2 : pk2;  int is2 = ow ? og2 : pi2;   // winner-side 2nd
        int kl  = ow ? pk1 : cm1;  int il  = ow ? pi1 : og1;   // losing 1st
        bool sw2 = (ks > kl) || (ks == kl && is2 < il);
        int M2 = sw2 ? ks : kl;
        int I2 = sw2 ? is2 : il;
        float4 bb2 = bb1; float cls2 = cls1;
        if (M2 >= 0) {
            if (ow) {
                if (sw2) { bb2 = sbox[cl2]; cls2 = scls[cl2]; }
                else     { bb2 = make_float4(M[2], M[3], M[4], M[5]); cls2 = M[6]; }
            } else {
                if (sw2) { bb2 = make_float4(M[10], M[11], M[12], M[13]); cls2 = M[14]; }
                else     { bb2 = sbox[cl1]; cls2 = scls[cl1]; }
            }
        }

        float aa1 = (bb1.z - bb1.x) * (bb1.w - bb1.y);

        // lookahead: is the global 2nd-best the next reference winner?
        bool two = false; float aa2 = 0.0f;
        if (M2 >= 0 && ndet + 1 < MAX_DET) {
            float iy1 = fmaxf(bb1.x, bb2.x);
            float ixa = fmaxf(bb1.y, bb2.y);
            float iy2 = fminf(bb1.z, bb2.z);
            float ixb = fminf(bb1.w, bb2.w);
            float inter = fmaxf(iy2 - iy1, 0.0f) * fmaxf(ixb - ixa, 0.0f);
            float ab  = (bb2.z - bb2.x) * (bb2.w - bb2.y);
            float uni = aa1 + ab - inter;
            float d   = fmaf(-IOU_C, uni, inter);
            two = !(d > uni * HC);
            aa2 = ab;
        }

        if (rank == 0 && tid == 0) {
            out_boxes[ndet * 4 + 0] = bb1.x;
            out_boxes[ndet * 4 + 1] = bb1.y;
            out_boxes[ndet * 4 + 2] = bb1.z;
            out_boxes[ndet * 4 + 3] = bb1.w;
            out_cls[ndet] = cls1;
            out_sc[ndet]  = __int_as_float(M1);
            if (two) {
                out_boxes[(ndet + 1) * 4 + 0] = bb2.x;
                out_boxes[(ndet + 1) * 4 + 1] = bb2.y;
                out_boxes[(ndet + 1) * 4 + 2] = bb2.z;
                out_boxes[(ndet + 1) * 4 + 3] = bb2.w;
                out_cls[ndet + 1] = cls2;
                out_sc[ndet + 1]  = __int_as_float(M2);
            }
        }

        // ---- fused suppression + next top-2 over own half ----
        // Fast path: positive-area winners self-suppress via their own IoU test
        // (in == ab == aa exactly => e = 0.55*aa > aa*2^-26).
        bool bothpos = (aa1 > 0.0f) && (!two || aa2 > 0.0f);   // uniform
        if (tk1 > 0) {
            if (bothpos) { if (two) SCAN_BODY(1, 0) else SCAN_BODY(0, 0) }
            else         { if (two) SCAN_BODY(1, 1) else SCAN_BODY(0, 1) }
        }

        ndet += two ? 2 : 1;
        p ^= 1;
    }

    // tail zero-fill (out is poisoned; reference emits zeros for !ok slots)
    if (rank == 0) {
        for (int i = ndet + tid; i < MAX_DET; i += NT) {
            out_boxes[i * 4 + 0] = 0.0f;
            out_boxes[i * 4 + 1] = 0.0f;
            out_boxes[i * 4 + 2] = 0.0f;
            out_boxes[i * 4 + 3] = 0.0f;
            out_cls[i] = 0.0f;
            out_sc[i]  = 0.0f;
        }
        if (tid == 0) *out_nd = (float)ndet;
    }

    CLUSTER_ARRIVE(); CLUSTER_WAIT();    // no CTA exits while peer may signal it
}

extern "C" void kernel_launch(void* const* d_in, const int* in_sizes, int n_in,
                              void* d_out, int out_size)
{
    (void)in_sizes; (void)n_in; (void)out_size;
    const float* in = (const float*)d_in[0];
    float* out = (float*)d_out;

    cudaFuncSetAttribute(nms_kernel,
                         cudaFuncAttributeMaxDynamicSharedMemorySize, SMEM_BYTES);

    dim3 g1(P1_GRIDX, BATCH);
    decode_kernel<<<g1, P1_NT>>>(in);
    nms_kernel<<<2 * BATCH, NT, SMEM_BYTES>>>(out);
}

// round 7
// speedup vs baseline: 4.2119x; 1.1145x over previous
#include <cuda_runtime.h>
#include <cstdint>

#define NUM_CLASSES 32
#define MAX_DET     100
#define CONF        0.25f
#define IOU_C       0.45f
#define HC          1.4901161193847656e-8f   // 2^-26 = half-ulp(0.45f)
#define BATCH       64
#define ANCHORS     8400
#define NT          512
#define KPT         9
#define HALF        (NT * KPT)               // 4608 anchors per CTA
#define PADDED      (2 * HALF)               // 9216
#define NWARPS      (NT / 32)                // 16
#define NEG_INF_I   ((int)0x80000000)

#define P1_NT       512
#define P1_GRIDX    (PADDED / P1_NT)         // 18

// scratch (allocation-free rule: __device__ globals)
__device__ float4 g_box[BATCH * PADDED];
__device__ float  g_sc [BATCH * PADDED];
__device__ float  g_cls[BATCH * PADDED];

// NMS dynamic smem per CTA: FULL float4 boxes[9216] | FULL float cls[9216]
#define SMEM_BYTES (PADDED * 16 + PADDED * 4)

// ---------------- cluster / mbarrier helpers ----------------
__device__ __forceinline__ uint32_t smem_u32(const void* p) {
    uint32_t a;
    asm("{ .reg .u64 t; cvta.to.shared.u64 t, %1; cvt.u32.u64 %0, t; }" : "=r"(a) : "l"(p));
    return a;
}
__device__ __forceinline__ uint32_t mapa_peer(uint32_t laddr, uint32_t peer) {
    uint32_t r;
    asm("mapa.shared::cluster.u32 %0, %1, %2;" : "=r"(r) : "r"(laddr), "r"(peer));
    return r;
}
__device__ __forceinline__ void st_peer_u32(uint32_t raddr, uint32_t v) {
    asm volatile("st.shared::cluster.u32 [%0], %1;" :: "r"(raddr), "r"(v) : "memory");
}
__device__ __forceinline__ void mbar_init(uint32_t a, uint32_t cnt) {
    asm volatile("mbarrier.init.shared.b64 [%0], %1;" :: "r"(a), "r"(cnt) : "memory");
}
// release.cluster arrive on the PEER's mbarrier: orders our st.shared::cluster
// mailbox writes before the arrival (replaces fence.acq_rel.cluster).
__device__ __forceinline__ void mbar_arrive_peer_rel(uint32_t laddr, uint32_t peer) {
    asm volatile("{\n\t.reg .b32 r;\n\t"
                 "mapa.shared::cluster.u32 r, %0, %1;\n\t"
                 "mbarrier.arrive.release.cluster.shared::cluster.b64 _, [r];\n\t}"
                 :: "r"(laddr), "r"(peer) : "memory");
}
// acquire.cluster wait: pairs with the peer's release-arrive.
__device__ __forceinline__ void mbar_wait_acq(uint32_t a, uint32_t parity) {
    uint32_t done;
    asm volatile("{\n\t.reg .pred p;\n\t"
                 "mbarrier.try_wait.parity.acquire.cluster.shared::cta.b64 p, [%1], %2;\n\t"
                 "selp.b32 %0, 1, 0, p;\n\t}"
                 : "=r"(done) : "r"(a), "r"(parity) : "memory");
    if (!done) {
        asm volatile("{\n\t.reg .pred P1;\n\t"
                     "WL_%=:\n\t"
                     "mbarrier.try_wait.parity.acquire.cluster.shared::cta.b64 P1, [%0], %1;\n\t"
                     "@P1 bra.uni WD_%=;\n\t"
                     "bra.uni WL_%=;\n\t"
                     "WD_%=:\n\t}"
                     :: "r"(a), "r"(parity) : "memory");
    }
}
#define CLUSTER_ARRIVE() asm volatile("barrier.cluster.arrive.aligned;" ::: "memory")
#define CLUSTER_WAIT()   asm volatile("barrier.cluster.wait.aligned;" ::: "memory")

// ---------------- Phase 1: full-chip decode ----------------
__global__ __launch_bounds__(P1_NT)
void decode_kernel(const float* __restrict__ in)
{
    const int a = blockIdx.x * P1_NT + threadIdx.x;   // 0..9215
    const int b = blockIdx.y;
    const size_t o = (size_t)b * PADDED + a;

    if (a < ANCHORS) {
        const float* base = in + (size_t)b * (4 + NUM_CLASSES) * ANCHORS;
        float xc = base[0 * ANCHORS + a];
        float yc = base[1 * ANCHORS + a];
        float w  = base[2 * ANCHORS + a];
        float h  = base[3 * ANCHORS + a];

        float bs = base[4 * ANCHORS + a];
        int   bc = 0;
        #pragma unroll
        for (int c = 1; c < NUM_CLASSES; c++) {
            float v = base[(4 + c) * ANCHORS + a];
            if (v > bs) { bs = v; bc = c; }   // strict > = first max (jnp.argmax)
        }

        float hw = w * 0.5f;
        float hh = h * 0.5f;
        float y1 = fminf(fmaxf(yc - hh, 0.0f), 1.0f);
        float x1 = fminf(fmaxf(xc - hw, 0.0f), 1.0f);
        float y2 = fminf(fmaxf(yc + hh, 0.0f), 1.0f);
        float x2 = fminf(fmaxf(xc + hw, 0.0f), 1.0f);

        g_box[o] = make_float4(y1, x1, y2, x2);
        g_sc[o]  = (bs >= CONF) ? bs : -1.0f;
        g_cls[o] = (float)bc;
    } else {
        g_box[o] = make_float4(0.0f, 0.0f, 0.0f, 0.0f);
        g_sc[o]  = -1.0f;
        g_cls[o] = 0.0f;
    }
}

// suppression scan + next top-2; indices are GLOBAL anchor ids
#define SCAN_BODY(TWO, CHECK)                                                  \
{                                                                              \
    int nk1 = NEG_INF_I, ni1 = 0, nk2 = NEG_INF_I, ni2 = 0;                    \
    _Pragma("unroll")                                                          \
    for (int k = 0; k < KPT; k++) {                                            \
        float v = rsc[k];                                                      \
        float ab = rab[k];   /* bit-identical to per-iter recompute */         \
        float a1 = fmaxf(bb1.x, ry1[k]);                                       \
        float b1v= fmaxf(bb1.y, rx1[k]);                                       \
        float c1 = fminf(bb1.z, ry2[k]);                                       \
        float d1v= fminf(bb1.w, rx2[k]);                                       \
        float in1 = fmaxf(c1 - a1, 0.0f) * fmaxf(d1v - b1v, 0.0f);             \
        float u1  = aa1 + ab - in1;                                            \
        float e1  = fmaf(-IOU_C, u1, in1);                                     \
        bool sup = (e1 > u1 * HC);                                             \
        if (CHECK) sup = sup || (gbase + k == I1);                             \
        if (TWO) {                                                             \
            float a2 = fmaxf(bb2.x, ry1[k]);                                   \
            float b2v= fmaxf(bb2.y, rx1[k]);                                   \
            float c2 = fminf(bb2.z, ry2[k]);                                   \
            float d2v= fminf(bb2.w, rx2[k]);                                   \
            float in2 = fmaxf(c2 - a2, 0.0f) * fmaxf(d2v - b2v, 0.0f);         \
            float u2  = aa2 + ab - in2;                                        \
            float e2  = fmaf(-IOU_C, u2, in2);                                 \
            bool s2 = (e2 > u2 * HC);                                          \
            if (CHECK) s2 = s2 || (gbase + k == I2);                           \
            sup = sup || s2;                                                   \
        }                                                                      \
        v = sup ? -1.0f : v;                                                   \
        rsc[k] = v;                                                            \
        int ik = __float_as_int(v);                                            \
        if (ik > nk1)      { nk2 = nk1; ni2 = ni1; nk1 = ik; ni1 = gbase + k; }\
        else if (ik > nk2) { nk2 = ik; ni2 = gbase + k; }                      \
    }                                                                          \
    tk1 = nk1; ti1 = ni1; tk2 = nk2; ti2 = ni2;                                \
}

// ---------------- Phase 2: 2-CTA-cluster NMS, key/idx-only exchange ----------------
__global__ __launch_bounds__(NT, 1) __cluster_dims__(2, 1, 1)
void nms_kernel(float* __restrict__ out)
{
    extern __shared__ char smem[];
    float4* sbox = reinterpret_cast<float4*>(smem);                 // FULL boxes
    float*  scls = reinterpret_cast<float*>(smem + PADDED * 16);    // FULL classes

    __shared__ int red_k[2][2 * NWARPS];     // double-buffered warp top-2 (32 entries)
    __shared__ int red_i[2][2 * NWARPS];
    __shared__ __align__(16) int s_mail[2][4];   // [parity][k1,i1,k2,i2], peer-written
    __shared__ uint64_t s_mbar[2];

    const int tid  = threadIdx.x;
    const int lane = tid & 31;
    const int wid  = tid >> 5;
    const unsigned FULL = 0xffffffffu;
    uint32_t rank;
    asm("mov.u32 %0, %%cluster_ctarank;" : "=r"(rank));
    const uint32_t peer = rank ^ 1;
    const int b = blockIdx.x >> 1;

    const uint32_t mb0   = smem_u32(&s_mbar[0]);
    const uint32_t mb1   = smem_u32(&s_mbar[1]);
    const uint32_t mail0 = smem_u32(&s_mail[0][0]);
    const uint32_t mail1 = smem_u32(&s_mail[1][0]);

    if (tid == 0) { mbar_init(mb0, 1); mbar_init(mb1, 1); }

    // coalesced fill of the FULL arrays (both CTAs replicate)
    const float4* gb = g_box + (size_t)b * PADDED;
    const float*  gc = g_cls + (size_t)b * PADDED;
    for (int a = tid; a < PADDED; a += NT) { sbox[a] = gb[a]; scls[a] = gc[a]; }
    __syncthreads();

    CLUSTER_ARRIVE(); CLUSTER_WAIT();        // mbarrier init visible cluster-wide

    // register slice: this CTA owns global anchors [rank*HALF + t*9, +9)
    float ry1[KPT], rx1[KPT], ry2[KPT], rx2[KPT], rsc[KPT], rab[KPT];
    const int gbase = (int)rank * HALF + tid * KPT;
    const float* gs = g_sc + (size_t)b * PADDED + gbase;
    int tk1 = NEG_INF_I, ti1 = 0, tk2 = NEG_INF_I, ti2 = 0;
    #pragma unroll
    for (int k = 0; k < KPT; k++) {
        float4 v = sbox[gbase + k];
        ry1[k] = v.x; rx1[k] = v.y; ry2[k] = v.z; rx2[k] = v.w;
        rab[k] = (v.z - v.x) * (v.w - v.y);
        float sv = gs[k];
        rsc[k] = sv;
        int ik = __float_as_int(sv);
        if (ik > tk1)      { tk2 = tk1; ti2 = ti1; tk1 = ik; ti1 = gbase + k; }
        else if (ik > tk2) { tk2 = ik; ti2 = gbase + k; }
    }

    float* out_boxes = out + (size_t)b * MAX_DET * 4;
    float* out_cls   = out + (size_t)BATCH * MAX_DET * 4 + (size_t)b * MAX_DET;
    float* out_sc    = out + (size_t)BATCH * MAX_DET * 5 + (size_t)b * MAX_DET;
    float* out_nd    = out + (size_t)BATCH * MAX_DET * 6 + b;

    int ndet = 0, p = 0, ph0 = 0, ph1 = 0;
    while (ndet < MAX_DET) {
        // ---- warp top-2 over global indices (redux + ballot) ----
        int m1 = __reduce_max_sync(FULL, tk1);
        unsigned ball = __ballot_sync(FULL, tk1 == m1);
        int src = __ffs(ball) - 1;                 // lowest lane = smallest global idx
        int wi1 = __shfl_sync(FULL, ti1, src);
        int kx = (lane == src) ? tk2 : tk1;
        int ix = (lane == src) ? ti2 : ti1;
        int m2w = __reduce_max_sync(FULL, kx);
        ball = __ballot_sync(FULL, kx == m2w);
        src  = __ffs(ball) - 1;
        int wi2 = __shfl_sync(FULL, ix, src);
        if (lane == 0) {
            red_k[p][2 * wid]     = m1;  red_i[p][2 * wid]     = wi1;
            red_k[p][2 * wid + 1] = m2w; red_i[p][2 * wid + 1] = wi2;
        }
        __syncthreads();

        // ---- CTA top-2 over 32 entries (every warp, redundantly) ----
        int ek = red_k[p][lane];
        int ei = red_i[p][lane];
        int cm1 = __reduce_max_sync(FULL, ek);
        ball = __ballot_sync(FULL, ek == cm1);
        src  = __ffs(ball) - 1;
        int cg1 = __shfl_sync(FULL, ei, src);       // global idx of CTA 1st
        int ekx = (lane == src) ? NEG_INF_I : ek;
        int cm2 = __reduce_max_sync(FULL, ekx);
        ball = __ballot_sync(FULL, ekx == cm2);
        int src2 = __ffs(ball) - 1;
        int cg2 = __shfl_sync(FULL, ei, src2);

        // ---- exchange CTA top-2 keys/indices with peer ----
        // Parity double-buffer: rewriting peer mail[p] at pass t is safe since
        // our pass t-1 wait on mbar[p^1] required the peer's arrive, program-
        // ordered after the peer's pass t-2 reads of mail[p]. Release-arrive /
        // acquire-wait order the mailbox stores (no separate fences needed).
        uint32_t mail = p ? mail1 : mail0;
        uint32_t mb   = p ? mb1   : mb0;
        if (tid == 0) {
            uint32_t r = mapa_peer(mail, peer);
            st_peer_u32(r +  0, (uint32_t)cm1);
            st_peer_u32(r +  4, (uint32_t)cg1);
            st_peer_u32(r +  8, (uint32_t)cm2);
            st_peer_u32(r + 12, (uint32_t)cg2);
            mbar_arrive_peer_rel(mb, peer);
        }
        mbar_wait_acq(mb, (uint32_t)(p ? ph1 : ph0));
        if (p) ph1 ^= 1; else ph0 ^= 1;

        // ---- symmetric merge of {own top-2} U {peer top-2} ----
        int pk1 = s_mail[p][0];
        int pi1 = s_mail[p][1];
        int pk2 = s_mail[p][2];
        int pi2 = s_mail[p][3];

        bool ow = (cm1 > pk1) || (cm1 == pk1 && cg1 < pi1);
        int M1 = ow ? cm1 : pk1;
        int I1 = ow ? cg1 : pi1;
        if (M1 < 0) break;                   // symmetric data -> uniform break

        int ks  = ow ? cm2 : pk2;  int is2 = ow ? cg2 : pi2;   // winner-side 2nd
        int kl  = ow ? pk1 : cm1;  int il  = ow ? pi1 : cg1;   // losing 1st
        bool sw2 = (ks > kl) || (ks == kl && is2 < il);
        int M2 = sw2 ? ks : kl;
        int I2 = sw2 ? is2 : il;

        float4 bb1 = sbox[I1];               // local lookup (arrays replicated)
        float aa1 = (bb1.z - bb1.x) * (bb1.w - bb1.y);

        // lookahead: is the global 2nd-best the next reference winner?
        bool two = false; float aa2 = 0.0f;
        float4 bb2 = bb1;
        if (M2 >= 0 && ndet + 1 < MAX_DET) {
            bb2 = sbox[I2];
            float iy1 = fmaxf(bb1.x, bb2.x);
            float ixa = fmaxf(bb1.y, bb2.y);
            float iy2 = fminf(bb1.z, bb2.z);
            float ixb = fminf(bb1.w, bb2.w);
            float inter = fmaxf(iy2 - iy1, 0.0f) * fmaxf(ixb - ixa, 0.0f);
            float ab  = (bb2.z - bb2.x) * (bb2.w - bb2.y);
            float uni = aa1 + ab - inter;
            float d   = fmaf(-IOU_C, uni, inter);
            two = !(d > uni * HC);
            aa2 = ab;
        }

        if (rank == 0 && tid == 0) {
            out_boxes[ndet * 4 + 0] = bb1.x;
            out_boxes[ndet * 4 + 1] = bb1.y;
            out_boxes[ndet * 4 + 2] = bb1.z;
            out_boxes[ndet * 4 + 3] = bb1.w;
            out_cls[ndet] = scls[I1];
            out_sc[ndet]  = __int_as_float(M1);
            if (two) {
                out_boxes[(ndet + 1) * 4 + 0] = bb2.x;
                out_boxes[(ndet + 1) * 4 + 1] = bb2.y;
                out_boxes[(ndet + 1) * 4 + 2] = bb2.z;
                out_boxes[(ndet + 1) * 4 + 3] = bb2.w;
                out_cls[ndet + 1] = scls[I2];
                out_sc[ndet + 1]  = __int_as_float(M2);
            }
        }

        // ---- fused suppression + next top-2 over own half ----
        // Fast path: positive-area winners self-suppress via their own IoU test
        // (in == ab == aa exactly => e = 0.55*aa > aa*2^-26).
        bool bothpos = (aa1 > 0.0f) && (!two || aa2 > 0.0f);   // uniform
        if (tk1 > 0) {
            if (bothpos) { if (two) SCAN_BODY(1, 0) else SCAN_BODY(0, 0) }
            else         { if (two) SCAN_BODY(1, 1) else SCAN_BODY(0, 1) }
        }

        ndet += two ? 2 : 1;
        p ^= 1;
    }

    // tail zero-fill (out is poisoned; reference emits zeros for !ok slots)
    if (rank == 0) {
        for (int i = ndet + tid; i < MAX_DET; i += NT) {
            out_boxes[i * 4 + 0] = 0.0f;
            out_boxes[i * 4 + 1] = 0.0f;
            out_boxes[i * 4 + 2] = 0.0f;
            out_boxes[i * 4 + 3] = 0.0f;
            out_cls[i] = 0.0f;
            out_sc[i]  = 0.0f;
        }
        if (tid == 0) *out_nd = (float)ndet;
    }

    CLUSTER_ARRIVE(); CLUSTER_WAIT();    // no CTA exits while peer may signal it
}

extern "C" void kernel_launch(void* const* d_in, const int* in_sizes, int n_in,
                              void* d_out, int out_size)
{
    (void)in_sizes; (void)n_in; (void)out_size;
    const float* in = (const float*)d_in[0];
    float* out = (float*)d_out;

    cudaFuncSetAttribute(nms_kernel,
                         cudaFuncAttributeMaxDynamicSharedMemorySize, SMEM_BYTES);

    dim3 g1(P1_GRIDX, BATCH);
    decode_kernel<<<g1, P1_NT>>>(in);
    nms_kernel<<<2 * BATCH, NT, SMEM_BYTES>>>(out);
}